// round 16
// baseline (speedup 1.0000x reference)
#include <cuda_runtime.h>
#include <cuda_fp16.h>

#define NN 4096
#define NE 65536
#define FEA 512
#define GW 128
#define GH 64      // GW/2 half2 per row
#define CAP 128

// ---- scratch (static device globals; zero-initialized at load) ----
__device__ unsigned g_Ah[NN * GH];   // half2-packed 0.5*(relu(T)@Wt^T + b)
__device__ unsigned g_Bh[NN * GH];   // half2-packed 0.5*(relu(S)@Ws^T)
__device__ __half   g_S16[NN * FEA]; // fp16 copy of source_features
__device__ int      g_cnt[NN];       // in-degree; self-cleaned by k_gateout
__device__ int      g_bkt[NN * CAP]; // stores SOURCE INDEX per slot

__device__ __forceinline__ unsigned tanh2(unsigned x) {
    unsigned y; asm("tanh.approx.f16x2 %0, %1;" : "=r"(y) : "r"(x)); return y;
}
__device__ __forceinline__ unsigned hadd2u(unsigned a, unsigned b) {
    unsigned y; asm("add.rn.f16x2 %0, %1, %2;" : "=r"(y) : "r"(a), "r"(b)); return y;
}
__device__ __forceinline__ unsigned smem_u32(const void* p) {
    unsigned r;
    asm("{ .reg .u64 t; cvta.to.shared.u64 t, %1; cvt.u32.u64 %0, t; }"
        : "=r"(r) : "l"(p));
    return r;
}
__device__ __forceinline__ void ldm_x4(unsigned* r, unsigned addr) {
    asm volatile("ldmatrix.sync.aligned.m8n8.x4.shared.b16 {%0,%1,%2,%3}, [%4];"
                 : "=r"(r[0]), "=r"(r[1]), "=r"(r[2]), "=r"(r[3]) : "r"(addr));
}
__device__ __forceinline__ void mma_f16(float* c, const unsigned* a,
                                        unsigned b0, unsigned b1) {
    asm("mma.sync.aligned.m16n8k16.row.col.f32.f16.f16.f32 "
        "{%0,%1,%2,%3}, {%4,%5,%6,%7}, {%8,%9}, {%0,%1,%2,%3};"
        : "+f"(c[0]), "+f"(c[1]), "+f"(c[2]), "+f"(c[3])
        : "r"(a[0]), "r"(a[1]), "r"(a[2]), "r"(a[3]), "r"(b0), "r"(b1));
}
__device__ __forceinline__ unsigned pack_h2(float x, float y) {
    __half2 h = __floats2half2_rn(x, y);
    return *(unsigned*)&h;
}

// ------------------------------------------------------------------
// Kernel 1: EXACT R15 version (best measured).
// blocks 0..127: fp16-MMA GEMMs -> half2 logits.
// blocks 128..191: bucket fill (stores si[e]) + FULL S->fp16 copy.
// ------------------------------------------------------------------
#define BM 64
#define BK 32
#define SH 40    // smem row stride in halves: conflict-free ldmatrix

__global__ __launch_bounds__(256) void k_work(
    const float* __restrict__ T, const float* __restrict__ S,
    const float* __restrict__ w, const float* __restrict__ b,
    const int* __restrict__ ti, const int* __restrict__ si) {
    __shared__ __half sF[BM * SH];
    __shared__ __half sW[GW * SH];

    int blk = blockIdx.x;
    int tid = threadIdx.x;

    if (blk >= 128) {
        int base = (blk - 128) * 256 + tid;       // 0..16383
        int e0 = base * 4;
        int4 t = *(const int4*)(ti + e0);
        int4 s = *(const int4*)(si + e0);
        int p;
        p = atomicAdd(&g_cnt[t.x], 1); if (p < CAP) g_bkt[t.x * CAP + p] = s.x;
        p = atomicAdd(&g_cnt[t.y], 1); if (p < CAP) g_bkt[t.y * CAP + p] = s.y;
        p = atomicAdd(&g_cnt[t.z], 1); if (p < CAP) g_bkt[t.z * CAP + p] = s.z;
        p = atomicAdd(&g_cnt[t.w], 1); if (p < CAP) g_bkt[t.w * CAP + p] = s.w;
#pragma unroll 8
        for (int j = 0; j < 32; j++) {
            int idx = base + j * 16384;
            float4 v = ((const float4*)S)[idx];
            uint2 u = make_uint2(pack_h2(v.x, v.y), pack_h2(v.z, v.w));
            ((uint2*)g_S16)[idx] = u;
        }
        return;
    }

    // ---------------- GEMM (exact R8) ----------------
    int which = blk >> 6;
    int mbase = (blk & 63) * BM;
    const float* F = which ? S : T;
    const float* W = w + (which ? FEA : 0);

    int warp = tid >> 5;
    int lane = tid & 31;
    int m0 = (warp >> 1) * 16;
    int n0 = (warp & 1) * 64;
    int g = lane >> 2;
    int tg = lane & 3;

    unsigned sF_base = smem_u32(sF);
    unsigned sW_base = smem_u32(sW);

    int rowA = m0 + (lane & 7) + ((lane >> 3) & 1) * 8;
    unsigned addrA0 = sF_base + rowA * (SH * 2) + (lane >> 4) * 16;
    unsigned addrB0[4];
#pragma unroll
    for (int p = 0; p < 4; p++) {
        int rowB = n0 + p * 16 + (lane >> 4) * 8 + (lane & 7);
        addrB0[p] = sW_base + rowB * (SH * 2) + ((lane >> 3) & 1) * 16;
    }

    int fr[2], fq[2], wr_[4], wq[4];
#pragma unroll
    for (int p = 0; p < 2; p++) { int idx = tid + p * 256; fr[p] = idx >> 3; fq[p] = idx & 7; }
#pragma unroll
    for (int p = 0; p < 4; p++) { int idx = tid + p * 256; wr_[p] = idx >> 3; wq[p] = idx & 7; }

    float cacc[8][4];
#pragma unroll
    for (int i = 0; i < 8; i++)
#pragma unroll
        for (int j = 0; j < 4; j++) cacc[i][j] = 0.f;

    float4 pf[2], pw[4];
#pragma unroll
    for (int p = 0; p < 2; p++)
        pf[p] = *(const float4*)(F + (mbase + fr[p]) * FEA + fq[p] * 4);
#pragma unroll
    for (int p = 0; p < 4; p++)
        pw[p] = *(const float4*)(W + wr_[p] * (2 * FEA) + wq[p] * 4);

    for (int k0 = 0; k0 < FEA; k0 += BK) {
#pragma unroll
        for (int p = 0; p < 2; p++) {
            float4 f = pf[p];
            uint2 u = make_uint2(pack_h2(fmaxf(f.x, 0.f), fmaxf(f.y, 0.f)),
                                 pack_h2(fmaxf(f.z, 0.f), fmaxf(f.w, 0.f)));
            *(uint2*)&sF[fr[p] * SH + fq[p] * 4] = u;
        }
#pragma unroll
        for (int p = 0; p < 4; p++) {
            float4 v = pw[p];
            uint2 u = make_uint2(pack_h2(v.x, v.y), pack_h2(v.z, v.w));
            *(uint2*)&sW[wr_[p] * SH + wq[p] * 4] = u;
        }
        __syncthreads();

        int kn = k0 + BK;
        if (kn < FEA) {
#pragma unroll
            for (int p = 0; p < 2; p++)
                pf[p] = *(const float4*)(F + (mbase + fr[p]) * FEA + kn + fq[p] * 4);
#pragma unroll
            for (int p = 0; p < 4; p++)
                pw[p] = *(const float4*)(W + wr_[p] * (2 * FEA) + kn + wq[p] * 4);
        }

#pragma unroll
        for (int kk = 0; kk < BK; kk += 16) {
            unsigned a[4];
            ldm_x4(a, addrA0 + kk * 2);
#pragma unroll
            for (int p = 0; p < 4; p++) {
                unsigned bb[4];
                ldm_x4(bb, addrB0[p] + kk * 2);
                mma_f16(cacc[2 * p + 0], a, bb[0], bb[1]);
                mma_f16(cacc[2 * p + 1], a, bb[2], bb[3]);
            }
        }
        __syncthreads();
    }

    unsigned* O = which ? g_Bh : g_Ah;
#pragma unroll
    for (int nf = 0; nf < 8; nf++) {
        int col = n0 + nf * 8 + 2 * tg;
        int hcol = col >> 1;
        float bx = 0.f, by = 0.f;
        if (!which) {
            float2 braw = *(const float2*)(b + col);
            bx = 0.5f * braw.x; by = 0.5f * braw.y;
        }
        O[(mbase + m0 + g) * GH + hcol] =
            pack_h2(0.5f * cacc[nf][0] + bx, 0.5f * cacc[nf][1] + by);
        O[(mbase + m0 + g + 8) * GH + hcol] =
            pack_h2(0.5f * cacc[nf][2] + bx, 0.5f * cacc[nf][3] + by);
    }
}

// ------------------------------------------------------------------
// Kernel 2: R15 with ONLY phase 1 changed — single LDG.64 per lane
// and packed f16x2 shuffle reduction (gate sum is lane-order
// invariant, so the uint2 repacking is exact).
// ------------------------------------------------------------------
__global__ __launch_bounds__(128) void k_gateout(float* __restrict__ out) {
    __shared__ unsigned sA[GH];
    __shared__ int      s_sid[CAP];
    __shared__ float    s_g[CAP];

    int n = blockIdx.x;
    int t = threadIdx.x;
    int cnt = g_cnt[n];
    cnt = (cnt > CAP) ? CAP : cnt;

    if (t < GH) sA[t] = g_Ah[n * GH + t];
    if (t < cnt) s_sid[t] = g_bkt[n * CAP + t];
    __syncthreads();
    if (t == 0) g_cnt[n] = 0;   // self-clean for next graph replay

    // ---- phase 1: warp-per-edge, LDG.64 + packed f16x2 reduction ----
    int warp = t >> 5, lane = t & 31;
    uint2 av = *(const uint2*)&sA[lane * 2];
    for (int i = warp; i < cnt; i += 4) {
        uint2 bv = ((const uint2*)(g_Bh + s_sid[i] * GH))[lane];
        unsigned s = hadd2u(tanh2(hadd2u(av.x, bv.x)),
                            tanh2(hadd2u(av.y, bv.y)));
#pragma unroll
        for (int o = 16; o; o >>= 1)
            s = hadd2u(s, __shfl_xor_sync(0xffffffffu, s, o));
        if (lane == 0) {
            float2 f = __half22float2(*(__half2*)&s);
            s_g[i] = 0.5f + (f.x + f.y) * (0.5f / 128.f);
        }
    }
    __syncthreads();

    // ---- phase 2: EXACT R15 ----
    float4 accA = make_float4(0.f, 0.f, 0.f, 0.f);
    float4 accB = make_float4(0.f, 0.f, 0.f, 0.f);
    int i = 0;
    for (; i + 8 <= cnt; i += 8) {
        uint2 r[8];
#pragma unroll
        for (int j = 0; j < 8; j++)
            r[j] = *(const uint2*)(g_S16 + s_sid[i + j] * FEA + t * 4);
#pragma unroll
        for (int j = 0; j < 8; j++) {
            float gj = s_g[i + j];
            float2 f0 = __half22float2(*(__half2*)&r[j].x);
            float2 f1 = __half22float2(*(__half2*)&r[j].y);
            float4& ac = (j & 1) ? accB : accA;
            ac.x = fmaf(f0.x, gj, ac.x); ac.y = fmaf(f0.y, gj, ac.y);
            ac.z = fmaf(f1.x, gj, ac.z); ac.w = fmaf(f1.y, gj, ac.w);
        }
    }
    for (; i < cnt; i++) {
        uint2 rv = *(const uint2*)(g_S16 + s_sid[i] * FEA + t * 4);
        float gj = s_g[i];
        float2 f0 = __half22float2(*(__half2*)&rv.x);
        float2 f1 = __half22float2(*(__half2*)&rv.y);
        accA.x = fmaf(f0.x, gj, accA.x); accA.y = fmaf(f0.y, gj, accA.y);
        accA.z = fmaf(f1.x, gj, accA.z); accA.w = fmaf(f1.y, gj, accA.w);
    }
    float4 acc = make_float4(accA.x + accB.x, accA.y + accB.y,
                             accA.z + accB.z, accA.w + accB.w);
    float inv = (cnt > 0) ? (1.f / (float)cnt) : 0.f;
    acc.x *= inv; acc.y *= inv; acc.z *= inv; acc.w *= inv;
    *(float4*)(out + n * FEA + t * 4) = acc;
}

// ------------------------------------------------------------------
extern "C" void kernel_launch(void* const* d_in, const int* in_sizes, int n_in,
                              void* d_out, int out_size) {
    const float* T  = (const float*)d_in[0];
    const float* S  = (const float*)d_in[1];
    const float* w  = (const float*)d_in[2];
    const float* b  = (const float*)d_in[3];
    const int*   ti = (const int*)d_in[4];
    const int*   si = (const int*)d_in[5];
    float* out = (float*)d_out;

    k_work<<<192, 256>>>(T, S, w, b, ti, si);
    k_gateout<<<NN, 128>>>(out);
}

// round 17
// speedup vs baseline: 1.0114x; 1.0114x over previous
#include <cuda_runtime.h>
#include <cuda_fp16.h>

#define NN 4096
#define NE 65536
#define FEA 512
#define GW 128
#define GH 64      // GW/2 half2 per row
#define CAP 128

// ---- scratch (static device globals; zero-initialized at load) ----
__device__ unsigned g_Ah[NN * GH];   // half2-packed 0.5*(relu(T)@Wt^T + b)
__device__ unsigned g_Bh[NN * GH];   // half2-packed 0.5*(relu(S)@Ws^T)
__device__ __half   g_S16[NN * FEA]; // fp16 copy of source_features
__device__ int      g_cnt[NN];       // in-degree; self-cleaned by k_gateout
__device__ int      g_bkt[NN * CAP]; // stores SOURCE INDEX per slot

__device__ __forceinline__ unsigned tanh2(unsigned x) {
    unsigned y; asm("tanh.approx.f16x2 %0, %1;" : "=r"(y) : "r"(x)); return y;
}
__device__ __forceinline__ unsigned hadd2u(unsigned a, unsigned b) {
    unsigned y; asm("add.rn.f16x2 %0, %1, %2;" : "=r"(y) : "r"(a), "r"(b)); return y;
}
__device__ __forceinline__ unsigned smem_u32(const void* p) {
    unsigned r;
    asm("{ .reg .u64 t; cvta.to.shared.u64 t, %1; cvt.u32.u64 %0, t; }"
        : "=r"(r) : "l"(p));
    return r;
}
__device__ __forceinline__ void ldm_x4(unsigned* r, unsigned addr) {
    asm volatile("ldmatrix.sync.aligned.m8n8.x4.shared.b16 {%0,%1,%2,%3}, [%4];"
                 : "=r"(r[0]), "=r"(r[1]), "=r"(r[2]), "=r"(r[3]) : "r"(addr));
}
__device__ __forceinline__ void mma_f16(float* c, const unsigned* a,
                                        unsigned b0, unsigned b1) {
    asm("mma.sync.aligned.m16n8k16.row.col.f32.f16.f16.f32 "
        "{%0,%1,%2,%3}, {%4,%5,%6,%7}, {%8,%9}, {%0,%1,%2,%3};"
        : "+f"(c[0]), "+f"(c[1]), "+f"(c[2]), "+f"(c[3])
        : "r"(a[0]), "r"(a[1]), "r"(a[2]), "r"(a[3]), "r"(b0), "r"(b1));
}
__device__ __forceinline__ unsigned pack_h2(float x, float y) {
    __half2 h = __floats2half2_rn(x, y);
    return *(unsigned*)&h;
}

// ------------------------------------------------------------------
// Kernel 1: EXACT R15 version (best measured).
// blocks 0..127: fp16-MMA GEMMs -> half2 logits.
// blocks 128..191: bucket fill (stores si[e]) + FULL S->fp16 copy.
// ------------------------------------------------------------------
#define BM 64
#define BK 32
#define SH 40    // smem row stride in halves: conflict-free ldmatrix

__global__ __launch_bounds__(256) void k_work(
    const float* __restrict__ T, const float* __restrict__ S,
    const float* __restrict__ w, const float* __restrict__ b,
    const int* __restrict__ ti, const int* __restrict__ si) {
    __shared__ __half sF[BM * SH];
    __shared__ __half sW[GW * SH];

    int blk = blockIdx.x;
    int tid = threadIdx.x;

    if (blk >= 128) {
        int base = (blk - 128) * 256 + tid;       // 0..16383
        int e0 = base * 4;
        int4 t = *(const int4*)(ti + e0);
        int4 s = *(const int4*)(si + e0);
        int p;
        p = atomicAdd(&g_cnt[t.x], 1); if (p < CAP) g_bkt[t.x * CAP + p] = s.x;
        p = atomicAdd(&g_cnt[t.y], 1); if (p < CAP) g_bkt[t.y * CAP + p] = s.y;
        p = atomicAdd(&g_cnt[t.z], 1); if (p < CAP) g_bkt[t.z * CAP + p] = s.z;
        p = atomicAdd(&g_cnt[t.w], 1); if (p < CAP) g_bkt[t.w * CAP + p] = s.w;
#pragma unroll 8
        for (int j = 0; j < 32; j++) {
            int idx = base + j * 16384;
            float4 v = ((const float4*)S)[idx];
            uint2 u = make_uint2(pack_h2(v.x, v.y), pack_h2(v.z, v.w));
            ((uint2*)g_S16)[idx] = u;
        }
        return;
    }

    // ---------------- GEMM (exact R8) ----------------
    int which = blk >> 6;
    int mbase = (blk & 63) * BM;
    const float* F = which ? S : T;
    const float* W = w + (which ? FEA : 0);

    int warp = tid >> 5;
    int lane = tid & 31;
    int m0 = (warp >> 1) * 16;
    int n0 = (warp & 1) * 64;
    int g = lane >> 2;
    int tg = lane & 3;

    unsigned sF_base = smem_u32(sF);
    unsigned sW_base = smem_u32(sW);

    int rowA = m0 + (lane & 7) + ((lane >> 3) & 1) * 8;
    unsigned addrA0 = sF_base + rowA * (SH * 2) + (lane >> 4) * 16;
    unsigned addrB0[4];
#pragma unroll
    for (int p = 0; p < 4; p++) {
        int rowB = n0 + p * 16 + (lane >> 4) * 8 + (lane & 7);
        addrB0[p] = sW_base + rowB * (SH * 2) + ((lane >> 3) & 1) * 16;
    }

    int fr[2], fq[2], wr_[4], wq[4];
#pragma unroll
    for (int p = 0; p < 2; p++) { int idx = tid + p * 256; fr[p] = idx >> 3; fq[p] = idx & 7; }
#pragma unroll
    for (int p = 0; p < 4; p++) { int idx = tid + p * 256; wr_[p] = idx >> 3; wq[p] = idx & 7; }

    float cacc[8][4];
#pragma unroll
    for (int i = 0; i < 8; i++)
#pragma unroll
        for (int j = 0; j < 4; j++) cacc[i][j] = 0.f;

    float4 pf[2], pw[4];
#pragma unroll
    for (int p = 0; p < 2; p++)
        pf[p] = *(const float4*)(F + (mbase + fr[p]) * FEA + fq[p] * 4);
#pragma unroll
    for (int p = 0; p < 4; p++)
        pw[p] = *(const float4*)(W + wr_[p] * (2 * FEA) + wq[p] * 4);

    for (int k0 = 0; k0 < FEA; k0 += BK) {
#pragma unroll
        for (int p = 0; p < 2; p++) {
            float4 f = pf[p];
            uint2 u = make_uint2(pack_h2(fmaxf(f.x, 0.f), fmaxf(f.y, 0.f)),
                                 pack_h2(fmaxf(f.z, 0.f), fmaxf(f.w, 0.f)));
            *(uint2*)&sF[fr[p] * SH + fq[p] * 4] = u;
        }
#pragma unroll
        for (int p = 0; p < 4; p++) {
            float4 v = pw[p];
            uint2 u = make_uint2(pack_h2(v.x, v.y), pack_h2(v.z, v.w));
            *(uint2*)&sW[wr_[p] * SH + wq[p] * 4] = u;
        }
        __syncthreads();

        int kn = k0 + BK;
        if (kn < FEA) {
#pragma unroll
            for (int p = 0; p < 2; p++)
                pf[p] = *(const float4*)(F + (mbase + fr[p]) * FEA + kn + fq[p] * 4);
#pragma unroll
            for (int p = 0; p < 4; p++)
                pw[p] = *(const float4*)(W + wr_[p] * (2 * FEA) + kn + wq[p] * 4);
        }

#pragma unroll
        for (int kk = 0; kk < BK; kk += 16) {
            unsigned a[4];
            ldm_x4(a, addrA0 + kk * 2);
#pragma unroll
            for (int p = 0; p < 4; p++) {
                unsigned bb[4];
                ldm_x4(bb, addrB0[p] + kk * 2);
                mma_f16(cacc[2 * p + 0], a, bb[0], bb[1]);
                mma_f16(cacc[2 * p + 1], a, bb[2], bb[3]);
            }
        }
        __syncthreads();
    }

    unsigned* O = which ? g_Bh : g_Ah;
#pragma unroll
    for (int nf = 0; nf < 8; nf++) {
        int col = n0 + nf * 8 + 2 * tg;
        int hcol = col >> 1;
        float bx = 0.f, by = 0.f;
        if (!which) {
            float2 braw = *(const float2*)(b + col);
            bx = 0.5f * braw.x; by = 0.5f * braw.y;
        }
        O[(mbase + m0 + g) * GH + hcol] =
            pack_h2(0.5f * cacc[nf][0] + bx, 0.5f * cacc[nf][1] + by);
        O[(mbase + m0 + g + 8) * GH + hcol] =
            pack_h2(0.5f * cacc[nf][2] + bx, 0.5f * cacc[nf][3] + by);
    }
}

// ------------------------------------------------------------------
// Kernel 2: R16 phase-1 math (packed f16x2 + LDG.64), now with
// 4-deep batched gather loads (addresses independent after the sync,
// so issue 4 LDGs per warp before consuming any). Phase 2 exact R15.
// ------------------------------------------------------------------
__global__ __launch_bounds__(128) void k_gateout(float* __restrict__ out) {
    __shared__ unsigned sA[GH];
    __shared__ int      s_sid[CAP];
    __shared__ float    s_g[CAP];

    int n = blockIdx.x;
    int t = threadIdx.x;
    int cnt = g_cnt[n];
    cnt = (cnt > CAP) ? CAP : cnt;

    if (t < GH) sA[t] = g_Ah[n * GH + t];
    if (t < cnt) s_sid[t] = g_bkt[n * CAP + t];
    __syncthreads();
    if (t == 0) g_cnt[n] = 0;   // self-clean for next graph replay

    // ---- phase 1: warp-per-edge, 4-deep batched LDG.64 + f16x2 reduce ----
    int warp = t >> 5, lane = t & 31;
    uint2 av = *(const uint2*)&sA[lane * 2];
    for (int i0 = warp; i0 < cnt; i0 += 16) {
        uint2 bv[4];
#pragma unroll
        for (int j = 0; j < 4; j++) {
            int i = i0 + j * 4;
            if (i < cnt) bv[j] = ((const uint2*)(g_Bh + s_sid[i] * GH))[lane];
        }
#pragma unroll
        for (int j = 0; j < 4; j++) {
            int i = i0 + j * 4;          // warp-uniform predicate
            if (i < cnt) {
                unsigned s = hadd2u(tanh2(hadd2u(av.x, bv[j].x)),
                                    tanh2(hadd2u(av.y, bv[j].y)));
#pragma unroll
                for (int o = 16; o; o >>= 1)
                    s = hadd2u(s, __shfl_xor_sync(0xffffffffu, s, o));
                if (lane == 0) {
                    float2 f = __half22float2(*(__half2*)&s);
                    s_g[i] = 0.5f + (f.x + f.y) * (0.5f / 128.f);
                }
            }
        }
    }
    __syncthreads();

    // ---- phase 2: EXACT R15 ----
    float4 accA = make_float4(0.f, 0.f, 0.f, 0.f);
    float4 accB = make_float4(0.f, 0.f, 0.f, 0.f);
    int i = 0;
    for (; i + 8 <= cnt; i += 8) {
        uint2 r[8];
#pragma unroll
        for (int j = 0; j < 8; j++)
            r[j] = *(const uint2*)(g_S16 + s_sid[i + j] * FEA + t * 4);
#pragma unroll
        for (int j = 0; j < 8; j++) {
            float gj = s_g[i + j];
            float2 f0 = __half22float2(*(__half2*)&r[j].x);
            float2 f1 = __half22float2(*(__half2*)&r[j].y);
            float4& ac = (j & 1) ? accB : accA;
            ac.x = fmaf(f0.x, gj, ac.x); ac.y = fmaf(f0.y, gj, ac.y);
            ac.z = fmaf(f1.x, gj, ac.z); ac.w = fmaf(f1.y, gj, ac.w);
        }
    }
    for (; i < cnt; i++) {
        uint2 rv = *(const uint2*)(g_S16 + s_sid[i] * FEA + t * 4);
        float gj = s_g[i];
        float2 f0 = __half22float2(*(__half2*)&rv.x);
        float2 f1 = __half22float2(*(__half2*)&rv.y);
        accA.x = fmaf(f0.x, gj, accA.x); accA.y = fmaf(f0.y, gj, accA.y);
        accA.z = fmaf(f1.x, gj, accA.z); accA.w = fmaf(f1.y, gj, accA.w);
    }
    float4 acc = make_float4(accA.x + accB.x, accA.y + accB.y,
                             accA.z + accB.z, accA.w + accB.w);
    float inv = (cnt > 0) ? (1.f / (float)cnt) : 0.f;
    acc.x *= inv; acc.y *= inv; acc.z *= inv; acc.w *= inv;
    *(float4*)(out + n * FEA + t * 4) = acc;
}

// ------------------------------------------------------------------
extern "C" void kernel_launch(void* const* d_in, const int* in_sizes, int n_in,
                              void* d_out, int out_size) {
    const float* T  = (const float*)d_in[0];
    const float* S  = (const float*)d_in[1];
    const float* w  = (const float*)d_in[2];
    const float* b  = (const float*)d_in[3];
    const int*   ti = (const int*)d_in[4];
    const int*   si = (const int*)d_in[5];
    float* out = (float*)d_out;

    k_work<<<192, 256>>>(T, S, w, b, ti, si);
    k_gateout<<<NN, 128>>>(out);
}